// round 1
// baseline (speedup 1.0000x reference)
#include <cuda_runtime.h>
#include <math.h>

#define NN   100000
#define EE   1600000
#define INF_ 256
#define HIDF 64
#define OUTF 40
#define COEF 0.1f   // 2*MU/P = 2*0.1/2

// ---- scratch (device globals; no allocation allowed) ----
__device__ float g_h [NN*HIDF];   // relu(x@W1+b1)
__device__ float g_f1[NN*HIDF];   // agg / f after iter 1
__device__ float g_f2[NN*HIDF];   // agg / f after iter 2
__device__ float g_dis[NN];       // deg^{-1/2}
__device__ float g_alpha[NN];
__device__ float g_beta[NN];
__device__ int   g_deg[NN];
__device__ float g_ce[EE];        // per-edge coefficient

// ---------------------------------------------------------------------------
// zero helpers
__global__ void k_zero_f4(float4* p, int n4) {
    int i = blockIdx.x * blockDim.x + threadIdx.x;
    if (i < n4) p[i] = make_float4(0.f, 0.f, 0.f, 0.f);
}
__global__ void k_zero_int(int* p, int n) {
    int i = blockIdx.x * blockDim.x + threadIdx.x;
    if (i < n) p[i] = 0;
}

// ---------------------------------------------------------------------------
// degree via atomics on dst
__global__ void k_degree(const int* __restrict__ dst, int* __restrict__ deg, int E) {
    int e = blockIdx.x * blockDim.x + threadIdx.x;
    if (e < E) atomicAdd(&deg[dst[e]], 1);
}

// per-node coefficients (P==2 => M==1 exactly)
__global__ void k_nodecoef(const int* __restrict__ deg,
                           float* __restrict__ dis,
                           float* __restrict__ alpha,
                           float* __restrict__ beta, int n) {
    int i = blockIdx.x * blockDim.x + threadIdx.x;
    if (i >= n) return;
    int d = deg[i];
    float dm = (float)(d > 0 ? d : 1);
    dis[i] = rsqrtf(dm);
    // denom = segsum(M)/deg + coef = (d>0 ? 1 : 0) + coef
    float denom = (d > 0 ? 1.0f : 0.0f) + COEF;
    float a = 1.0f / denom;
    alpha[i] = a;
    beta[i]  = COEF * a;
}

// per-edge coefficient c_e = dis[src]*dis[dst]
__global__ void k_edgecoef(const int* __restrict__ src, const int* __restrict__ dst,
                           const float* __restrict__ dis, float* __restrict__ ce, int E) {
    int e = blockIdx.x * blockDim.x + threadIdx.x;
    if (e < E) ce[e] = dis[src[e]] * dis[dst[e]];
}

// ---------------------------------------------------------------------------
// GEMM1 + ReLU: h[N,64] = relu(x[N,256] @ W1[256,64] + b1)
// 128 threads/block, 4 warps, 8 rows/warp, lane covers cols {l, l+32}.
__global__ __launch_bounds__(128) void k_gemm1(const float* __restrict__ x,
                                               const float* __restrict__ W1,
                                               const float* __restrict__ b1,
                                               float* __restrict__ h) {
    __shared__ float sx[32][INF_];          // 32 rows x 256 = 32KB
    int row0 = blockIdx.x * 32;
    int tid  = threadIdx.x;

    // cooperative load of 32 x-rows (float4)
    for (int i = tid; i < 32 * (INF_ / 4); i += 128) {
        int r = i / (INF_ / 4);
        int c = i % (INF_ / 4);
        float4 v = make_float4(0.f, 0.f, 0.f, 0.f);
        if (row0 + r < NN)
            v = *(const float4*)(x + (size_t)(row0 + r) * INF_ + c * 4);
        *(float4*)&sx[r][c * 4] = v;
    }
    __syncthreads();

    int warp = tid >> 5, lane = tid & 31;
    int r0 = warp * 8;

    float acc0[8], acc1[8];
#pragma unroll
    for (int r = 0; r < 8; r++) { acc0[r] = 0.f; acc1[r] = 0.f; }

#pragma unroll 4
    for (int k = 0; k < INF_; k++) {
        float w1a = W1[k * HIDF + lane];
        float w1b = W1[k * HIDF + lane + 32];
#pragma unroll
        for (int r = 0; r < 8; r++) {
            float xv = sx[r0 + r][k];
            acc0[r] = fmaf(xv, w1a, acc0[r]);
            acc1[r] = fmaf(xv, w1b, acc1[r]);
        }
    }

    float ba = b1[lane], bb = b1[lane + 32];
#pragma unroll
    for (int r = 0; r < 8; r++) {
        int row = row0 + r0 + r;
        if (row < NN) {
            h[(size_t)row * HIDF + lane]      = fmaxf(acc0[r] + ba, 0.f);
            h[(size_t)row * HIDF + lane + 32] = fmaxf(acc1[r] + bb, 0.f);
        }
    }
}

// ---------------------------------------------------------------------------
// SpMM scatter: agg[dst] += c_e * f[src], 16 threads/edge, float4 per thread
__global__ __launch_bounds__(256) void k_spmm(const float* __restrict__ f,
                                              const int* __restrict__ src,
                                              const int* __restrict__ dst,
                                              const float* __restrict__ ce,
                                              float* __restrict__ agg, int E) {
    int gid = blockIdx.x * blockDim.x + threadIdx.x;
    int e   = gid >> 4;
    if (e >= E) return;
    int sub = gid & 15;

    int   s = src[e];
    int   d = dst[e];
    float c = ce[e];

    float4 v = *(const float4*)(f + (size_t)s * HIDF + sub * 4);
    float* ap = agg + (size_t)d * HIDF + sub * 4;
    atomicAdd(ap + 0, c * v.x);
    atomicAdd(ap + 1, c * v.y);
    atomicAdd(ap + 2, c * v.z);
    atomicAdd(ap + 3, c * v.w);
}

// ---------------------------------------------------------------------------
// combine in place: agg[i] = alpha[node]*agg[i] + beta[node]*h[i]   (float4)
__global__ void k_combine(float* __restrict__ agg, const float* __restrict__ h,
                          const float* __restrict__ alpha, const float* __restrict__ beta) {
    int i = blockIdx.x * blockDim.x + threadIdx.x;    // one per float4
    if (i >= NN * (HIDF / 4)) return;
    int node = i / (HIDF / 4);
    float a = alpha[node], b = beta[node];
    float4 ag = ((float4*)agg)[i];
    float4 hv = ((const float4*)h)[i];
    ag.x = a * ag.x + b * hv.x;
    ag.y = a * ag.y + b * hv.y;
    ag.z = a * ag.z + b * hv.z;
    ag.w = a * ag.w + b * hv.w;
    ((float4*)agg)[i] = ag;
}

// ---------------------------------------------------------------------------
// GEMM2 + log_softmax, one warp per row.
// lane covers cols {l, l+32 (if l<8)}; f-row held as float2 per lane, shuffled.
__global__ __launch_bounds__(256) void k_out(const float* __restrict__ f,
                                             const float* __restrict__ W2,
                                             const float* __restrict__ b2,
                                             float* __restrict__ out) {
    int gwarp = (blockIdx.x * blockDim.x + threadIdx.x) >> 5;
    int lane  = threadIdx.x & 31;
    if (gwarp >= NN) return;

    float2 fr = ((const float2*)(f + (size_t)gwarp * HIDF))[lane];

    float acc0 = b2[lane];
    float acc1 = (lane < 8) ? b2[lane + 32] : -1e30f;

#pragma unroll
    for (int k = 0; k < HIDF; k++) {
        float fv = __shfl_sync(0xffffffffu, (k & 1) ? fr.y : fr.x, k >> 1);
        acc0 = fmaf(fv, W2[k * OUTF + lane], acc0);
        if (lane < 8) acc1 = fmaf(fv, W2[k * OUTF + lane + 32], acc1);
    }

    // log_softmax over 40 valid values
    float m = fmaxf(acc0, acc1);
#pragma unroll
    for (int o = 16; o > 0; o >>= 1) m = fmaxf(m, __shfl_xor_sync(0xffffffffu, m, o));
    float s = expf(acc0 - m) + ((lane < 8) ? expf(acc1 - m) : 0.f);
#pragma unroll
    for (int o = 16; o > 0; o >>= 1) s += __shfl_xor_sync(0xffffffffu, s, o);
    float ls = m + logf(s);

    out[(size_t)gwarp * OUTF + lane] = acc0 - ls;
    if (lane < 8) out[(size_t)gwarp * OUTF + lane + 32] = acc1 - ls;
}

// ---------------------------------------------------------------------------
extern "C" void kernel_launch(void* const* d_in, const int* in_sizes, int n_in,
                              void* d_out, int out_size) {
    const float* x   = (const float*)d_in[0];
    const int*   ei  = (const int*)  d_in[1];   // [2, E]
    const float* W1  = (const float*)d_in[2];
    const float* b1  = (const float*)d_in[3];
    const float* W2  = (const float*)d_in[4];
    const float* b2  = (const float*)d_in[5];
    float* out = (float*)d_out;

    const int E = in_sizes[1] / 2;              // 1600000
    const int* src = ei;
    const int* dst = ei + E;

    float *h, *f1, *f2, *dis, *alpha, *beta, *ce;
    int* deg;
    cudaGetSymbolAddress((void**)&h,     g_h);
    cudaGetSymbolAddress((void**)&f1,    g_f1);
    cudaGetSymbolAddress((void**)&f2,    g_f2);
    cudaGetSymbolAddress((void**)&dis,   g_dis);
    cudaGetSymbolAddress((void**)&alpha, g_alpha);
    cudaGetSymbolAddress((void**)&beta,  g_beta);
    cudaGetSymbolAddress((void**)&deg,   g_deg);
    cudaGetSymbolAddress((void**)&ce,    g_ce);

    const int NF4 = NN * HIDF / 4;

    // degrees + coefficients
    k_zero_int<<<(NN + 255) / 256, 256>>>(deg, NN);
    k_degree  <<<(E + 255) / 256, 256>>>(dst, deg, E);
    k_nodecoef<<<(NN + 255) / 256, 256>>>(deg, dis, alpha, beta, NN);
    k_edgecoef<<<(E + 255) / 256, 256>>>(src, dst, dis, ce, E);

    // h = relu(x @ W1 + b1)
    k_gemm1<<<(NN + 31) / 32, 128>>>(x, W1, b1, h);

    // iteration 1: f1 = alpha * (A_hat h) + beta * h
    k_zero_f4<<<(NF4 + 255) / 256, 256>>>((float4*)f1, NF4);
    k_spmm   <<<((E * 16) + 255) / 256, 256>>>(h, src, dst, ce, f1, E);
    k_combine<<<(NF4 + 255) / 256, 256>>>(f1, h, alpha, beta);

    // iteration 2: f2 = alpha * (A_hat f1) + beta * h
    k_zero_f4<<<(NF4 + 255) / 256, 256>>>((float4*)f2, NF4);
    k_spmm   <<<((E * 16) + 255) / 256, 256>>>(f1, src, dst, ce, f2, E);
    k_combine<<<(NF4 + 255) / 256, 256>>>(f2, h, alpha, beta);

    // out = log_softmax(f2 @ W2 + b2)
    k_out<<<(NN * 32 + 255) / 256, 256>>>(f2, W2, b2, out);
}

// round 2
// speedup vs baseline: 1.8891x; 1.8891x over previous
#include <cuda_runtime.h>
#include <math.h>

#define NN   100000
#define EE   1600000
#define INF_ 256
#define HIDF 64
#define OUTF 40
#define COEF 0.1f   // 2*MU/P

#define SCAN_B 1024
#define NB_SCAN ((NN + SCAN_B - 1) / SCAN_B)   // 98

// ---- scratch (device globals; no allocation allowed) ----
__device__ float g_h [NN*HIDF];
__device__ float g_f1[NN*HIDF];
__device__ float g_f2[NN*HIDF];
__device__ float g_dis[NN];
__device__ float g_alpha[NN];
__device__ float g_beta[NN];
__device__ int   g_deg[NN];
__device__ int   g_part[NN];      // per-block exclusive scan partials
__device__ int   g_bsum[NB_SCAN];
__device__ int   g_rowp[NN];      // CSR row start
__device__ int   g_cur[NN];       // fill cursors
__device__ int2  g_csr[EE];       // packed (src, dis[src])

// ---------------------------------------------------------------------------
__global__ void k_zero_int(int* p, int n) {
    int i = blockIdx.x * blockDim.x + threadIdx.x;
    if (i < n) p[i] = 0;
}

__global__ void k_degree(const int* __restrict__ dst, int* __restrict__ deg, int E) {
    int e = blockIdx.x * blockDim.x + threadIdx.x;
    if (e < E) atomicAdd(&deg[dst[e]], 1);
}

__global__ void k_nodecoef(const int* __restrict__ deg,
                           float* __restrict__ dis,
                           float* __restrict__ alpha,
                           float* __restrict__ beta, int n) {
    int i = blockIdx.x * blockDim.x + threadIdx.x;
    if (i >= n) return;
    int d = deg[i];
    float dm = (float)(d > 0 ? d : 1);
    dis[i] = rsqrtf(dm);
    float denom = (d > 0 ? 1.0f : 0.0f) + COEF;
    float a = 1.0f / denom;
    alpha[i] = a;
    beta[i]  = COEF * a;
}

// ---------------------------------------------------------------------------
// 3-kernel exclusive scan of degrees -> row_ptr
__global__ __launch_bounds__(SCAN_B) void k_scan1(const int* __restrict__ deg,
                                                  int* __restrict__ part,
                                                  int* __restrict__ bsum) {
    __shared__ int s[SCAN_B];
    int i = blockIdx.x * SCAN_B + threadIdx.x;
    int v = (i < NN) ? deg[i] : 0;
    s[threadIdx.x] = v;
    __syncthreads();
#pragma unroll
    for (int off = 1; off < SCAN_B; off <<= 1) {
        int t = (threadIdx.x >= off) ? s[threadIdx.x - off] : 0;
        __syncthreads();
        s[threadIdx.x] += t;
        __syncthreads();
    }
    if (i < NN) part[i] = s[threadIdx.x] - v;            // exclusive
    if (threadIdx.x == SCAN_B - 1) bsum[blockIdx.x] = s[SCAN_B - 1];
}

__global__ __launch_bounds__(128) void k_scan2(int* __restrict__ bsum, int nb) {
    __shared__ int s[128];
    int v = (threadIdx.x < nb) ? bsum[threadIdx.x] : 0;
    s[threadIdx.x] = v;
    __syncthreads();
#pragma unroll
    for (int off = 1; off < 128; off <<= 1) {
        int t = (threadIdx.x >= off) ? s[threadIdx.x - off] : 0;
        __syncthreads();
        s[threadIdx.x] += t;
        __syncthreads();
    }
    if (threadIdx.x < nb) bsum[threadIdx.x] = s[threadIdx.x] - v;   // exclusive
}

__global__ __launch_bounds__(SCAN_B) void k_scan3(const int* __restrict__ part,
                                                  const int* __restrict__ bsum,
                                                  int* __restrict__ rowp,
                                                  int* __restrict__ cur) {
    int i = blockIdx.x * SCAN_B + threadIdx.x;
    if (i < NN) {
        int r = part[i] + bsum[blockIdx.x];
        rowp[i] = r;
        cur[i]  = r;
    }
}

// ---------------------------------------------------------------------------
// CSR bucket fill: csr[pos] = (src, dis[src])
__global__ void k_fill(const int* __restrict__ src, const int* __restrict__ dst,
                       const float* __restrict__ dis,
                       int* __restrict__ cur, int2* __restrict__ csr, int E) {
    int e = blockIdx.x * blockDim.x + threadIdx.x;
    if (e >= E) return;
    int s = src[e];
    int d = dst[e];
    int pos = atomicAdd(&cur[d], 1);
    csr[pos] = make_int2(s, __float_as_int(dis[s]));
}

// ---------------------------------------------------------------------------
// GEMM1 + ReLU: h[N,64] = relu(x[N,256] @ W1[256,64] + b1)
__global__ __launch_bounds__(128) void k_gemm1(const float* __restrict__ x,
                                               const float* __restrict__ W1,
                                               const float* __restrict__ b1,
                                               float* __restrict__ h) {
    __shared__ float sx[32][INF_];
    int row0 = blockIdx.x * 32;
    int tid  = threadIdx.x;

    for (int i = tid; i < 32 * (INF_ / 4); i += 128) {
        int r = i / (INF_ / 4);
        int c = i % (INF_ / 4);
        float4 v = make_float4(0.f, 0.f, 0.f, 0.f);
        if (row0 + r < NN)
            v = *(const float4*)(x + (size_t)(row0 + r) * INF_ + c * 4);
        *(float4*)&sx[r][c * 4] = v;
    }
    __syncthreads();

    int warp = tid >> 5, lane = tid & 31;
    int r0 = warp * 8;

    float acc0[8], acc1[8];
#pragma unroll
    for (int r = 0; r < 8; r++) { acc0[r] = 0.f; acc1[r] = 0.f; }

#pragma unroll 4
    for (int k = 0; k < INF_; k++) {
        float w1a = W1[k * HIDF + lane];
        float w1b = W1[k * HIDF + lane + 32];
#pragma unroll
        for (int r = 0; r < 8; r++) {
            float xv = sx[r0 + r][k];
            acc0[r] = fmaf(xv, w1a, acc0[r]);
            acc1[r] = fmaf(xv, w1b, acc1[r]);
        }
    }

    float ba = b1[lane], bb = b1[lane + 32];
#pragma unroll
    for (int r = 0; r < 8; r++) {
        int row = row0 + r0 + r;
        if (row < NN) {
            h[(size_t)row * HIDF + lane]      = fmaxf(acc0[r] + ba, 0.f);
            h[(size_t)row * HIDF + lane + 32] = fmaxf(acc1[r] + bb, 0.f);
        }
    }
}

// ---------------------------------------------------------------------------
// Gather SpMM with fused combine: one warp per dst node.
// fout[d] = alpha[d]*dis[d] * sum_e dis[src]*f[src]  +  beta[d]*h[d]
__global__ __launch_bounds__(256) void k_spmm_csr(const float* __restrict__ f,
                                                  const float* __restrict__ h,
                                                  const int2* __restrict__ csr,
                                                  const int* __restrict__ rowp,
                                                  const int* __restrict__ deg,
                                                  const float* __restrict__ dis,
                                                  const float* __restrict__ alpha,
                                                  const float* __restrict__ beta,
                                                  float* __restrict__ fout) {
    int node = (blockIdx.x * blockDim.x + threadIdx.x) >> 5;
    if (node >= NN) return;
    int lane = threadIdx.x & 31;

    int beg = rowp[node];
    int n   = deg[node];

    float ax = 0.f, ay = 0.f;
    int i = 0;
    for (; i + 2 <= n; i += 2) {
        int2 e0 = csr[beg + i];
        int2 e1 = csr[beg + i + 1];
        float2 v0 = ((const float2*)(f + (size_t)e0.x * HIDF))[lane];
        float2 v1 = ((const float2*)(f + (size_t)e1.x * HIDF))[lane];
        float w0 = __int_as_float(e0.y);
        float w1 = __int_as_float(e1.y);
        ax = fmaf(w0, v0.x, ax); ay = fmaf(w0, v0.y, ay);
        ax = fmaf(w1, v1.x, ax); ay = fmaf(w1, v1.y, ay);
    }
    if (i < n) {
        int2 e0 = csr[beg + i];
        float2 v0 = ((const float2*)(f + (size_t)e0.x * HIDF))[lane];
        float w0 = __int_as_float(e0.y);
        ax = fmaf(w0, v0.x, ax); ay = fmaf(w0, v0.y, ay);
    }

    float scale = alpha[node] * dis[node];
    float b = beta[node];
    float2 hv = ((const float2*)(h + (size_t)node * HIDF))[lane];
    float2 r;
    r.x = fmaf(scale, ax, b * hv.x);
    r.y = fmaf(scale, ay, b * hv.y);
    ((float2*)(fout + (size_t)node * HIDF))[lane] = r;
}

// ---------------------------------------------------------------------------
// GEMM2 + log_softmax, one warp per row.
__global__ __launch_bounds__(256) void k_out(const float* __restrict__ f,
                                             const float* __restrict__ W2,
                                             const float* __restrict__ b2,
                                             float* __restrict__ out) {
    int gwarp = (blockIdx.x * blockDim.x + threadIdx.x) >> 5;
    int lane  = threadIdx.x & 31;
    if (gwarp >= NN) return;

    float2 fr = ((const float2*)(f + (size_t)gwarp * HIDF))[lane];

    float acc0 = b2[lane];
    float acc1 = (lane < 8) ? b2[lane + 32] : -1e30f;

#pragma unroll
    for (int k = 0; k < HIDF; k++) {
        float fv = __shfl_sync(0xffffffffu, (k & 1) ? fr.y : fr.x, k >> 1);
        acc0 = fmaf(fv, W2[k * OUTF + lane], acc0);
        if (lane < 8) acc1 = fmaf(fv, W2[k * OUTF + lane + 32], acc1);
    }

    float m = fmaxf(acc0, acc1);
#pragma unroll
    for (int o = 16; o > 0; o >>= 1) m = fmaxf(m, __shfl_xor_sync(0xffffffffu, m, o));
    float s = expf(acc0 - m) + ((lane < 8) ? expf(acc1 - m) : 0.f);
#pragma unroll
    for (int o = 16; o > 0; o >>= 1) s += __shfl_xor_sync(0xffffffffu, s, o);
    float ls = m + logf(s);

    out[(size_t)gwarp * OUTF + lane] = acc0 - ls;
    if (lane < 8) out[(size_t)gwarp * OUTF + lane + 32] = acc1 - ls;
}

// ---------------------------------------------------------------------------
extern "C" void kernel_launch(void* const* d_in, const int* in_sizes, int n_in,
                              void* d_out, int out_size) {
    const float* x   = (const float*)d_in[0];
    const int*   ei  = (const int*)  d_in[1];
    const float* W1  = (const float*)d_in[2];
    const float* b1  = (const float*)d_in[3];
    const float* W2  = (const float*)d_in[4];
    const float* b2  = (const float*)d_in[5];
    float* out = (float*)d_out;

    const int E = in_sizes[1] / 2;
    const int* src = ei;
    const int* dst = ei + E;

    float *h, *f1, *f2, *dis, *alpha, *beta;
    int *deg, *part, *bsum, *rowp, *cur;
    int2* csr;
    cudaGetSymbolAddress((void**)&h,     g_h);
    cudaGetSymbolAddress((void**)&f1,    g_f1);
    cudaGetSymbolAddress((void**)&f2,    g_f2);
    cudaGetSymbolAddress((void**)&dis,   g_dis);
    cudaGetSymbolAddress((void**)&alpha, g_alpha);
    cudaGetSymbolAddress((void**)&beta,  g_beta);
    cudaGetSymbolAddress((void**)&deg,   g_deg);
    cudaGetSymbolAddress((void**)&part,  g_part);
    cudaGetSymbolAddress((void**)&bsum,  g_bsum);
    cudaGetSymbolAddress((void**)&rowp,  g_rowp);
    cudaGetSymbolAddress((void**)&cur,   g_cur);
    cudaGetSymbolAddress((void**)&csr,   g_csr);

    // graph structure + coefficients
    k_zero_int<<<(NN + 255) / 256, 256>>>(deg, NN);
    k_degree  <<<(E + 255) / 256, 256>>>(dst, deg, E);
    k_nodecoef<<<(NN + 255) / 256, 256>>>(deg, dis, alpha, beta, NN);
    k_scan1   <<<NB_SCAN, SCAN_B>>>(deg, part, bsum);
    k_scan2   <<<1, 128>>>(bsum, NB_SCAN);
    k_scan3   <<<NB_SCAN, SCAN_B>>>(part, bsum, rowp, cur);
    k_fill    <<<(E + 255) / 256, 256>>>(src, dst, dis, cur, csr, E);

    // h = relu(x @ W1 + b1)
    k_gemm1<<<(NN + 31) / 32, 128>>>(x, W1, b1, h);

    // two propagation steps (gather SpMM + fused combine)
    k_spmm_csr<<<(NN * 32 + 255) / 256, 256>>>(h,  h, csr, rowp, deg, dis, alpha, beta, f1);
    k_spmm_csr<<<(NN * 32 + 255) / 256, 256>>>(f1, h, csr, rowp, deg, dis, alpha, beta, f2);

    // out = log_softmax(f2 @ W2 + b2)
    k_out<<<(NN * 32 + 255) / 256, 256>>>(f2, W2, b2, out);
}

// round 3
// speedup vs baseline: 2.0309x; 1.0751x over previous
#include <cuda_runtime.h>
#include <math.h>

#define NN   100000
#define EE   1600000
#define INF_ 256
#define HIDF 64
#define OUTF 40
#define COEF 0.1f   // 2*MU/P

#define SCAN_B 1024
#define NB_SCAN ((NN + SCAN_B - 1) / SCAN_B)   // 98

typedef unsigned long long u64;

// ---- scratch (device globals; no allocation allowed) ----
__device__ float g_h [NN*HIDF];
__device__ float g_f1[NN*HIDF];
__device__ float g_f2[NN*HIDF];
__device__ float g_dis[NN];
__device__ float g_alpha[NN];
__device__ float g_beta[NN];
__device__ int   g_deg[NN];
__device__ int   g_part[NN];
__device__ int   g_bsum[NB_SCAN];
__device__ int   g_rowp[NN];
__device__ int   g_cur[NN];
__device__ int2  g_csr[EE];       // packed (src, dis[src])

// ---------------------------------------------------------------------------
__device__ __forceinline__ u64 packff(float f) {
    u64 r;
    asm("mov.b64 %0, {%1, %1};" : "=l"(r) : "r"(__float_as_uint(f)));
    return r;
}
__device__ __forceinline__ void ffma2(u64& acc, u64 a, u64 b) {
    asm("fma.rn.f32x2 %0, %1, %2, %0;" : "+l"(acc) : "l"(a), "l"(b));
}
__device__ __forceinline__ float2 unpackff(u64 v) {
    unsigned lo, hi;
    asm("mov.b64 {%0, %1}, %2;" : "=r"(lo), "=r"(hi) : "l"(v));
    return make_float2(__uint_as_float(lo), __uint_as_float(hi));
}

// ---------------------------------------------------------------------------
__global__ void k_degree(const int* __restrict__ dst, int* __restrict__ deg, int E) {
    int e = blockIdx.x * blockDim.x + threadIdx.x;
    if (e < E) atomicAdd(&deg[dst[e]], 1);
}

__global__ void k_nodecoef(const int* __restrict__ deg,
                           float* __restrict__ dis,
                           float* __restrict__ alpha,
                           float* __restrict__ beta, int n) {
    int i = blockIdx.x * blockDim.x + threadIdx.x;
    if (i >= n) return;
    int d = deg[i];
    float dm = (float)(d > 0 ? d : 1);
    dis[i] = rsqrtf(dm);
    float denom = (d > 0 ? 1.0f : 0.0f) + COEF;
    float a = 1.0f / denom;
    alpha[i] = a;
    beta[i]  = COEF * a;
}

// ---------------------------------------------------------------------------
// 3-kernel exclusive scan of degrees -> row_ptr
__global__ __launch_bounds__(SCAN_B) void k_scan1(const int* __restrict__ deg,
                                                  int* __restrict__ part,
                                                  int* __restrict__ bsum) {
    __shared__ int s[SCAN_B];
    int i = blockIdx.x * SCAN_B + threadIdx.x;
    int v = (i < NN) ? deg[i] : 0;
    s[threadIdx.x] = v;
    __syncthreads();
#pragma unroll
    for (int off = 1; off < SCAN_B; off <<= 1) {
        int t = (threadIdx.x >= off) ? s[threadIdx.x - off] : 0;
        __syncthreads();
        s[threadIdx.x] += t;
        __syncthreads();
    }
    if (i < NN) part[i] = s[threadIdx.x] - v;
    if (threadIdx.x == SCAN_B - 1) bsum[blockIdx.x] = s[SCAN_B - 1];
}

__global__ __launch_bounds__(128) void k_scan2(int* __restrict__ bsum, int nb) {
    __shared__ int s[128];
    int v = (threadIdx.x < nb) ? bsum[threadIdx.x] : 0;
    s[threadIdx.x] = v;
    __syncthreads();
#pragma unroll
    for (int off = 1; off < 128; off <<= 1) {
        int t = (threadIdx.x >= off) ? s[threadIdx.x - off] : 0;
        __syncthreads();
        s[threadIdx.x] += t;
        __syncthreads();
    }
    if (threadIdx.x < nb) bsum[threadIdx.x] = s[threadIdx.x] - v;
}

__global__ __launch_bounds__(SCAN_B) void k_scan3(const int* __restrict__ part,
                                                  const int* __restrict__ bsum,
                                                  int* __restrict__ rowp,
                                                  int* __restrict__ cur) {
    int i = blockIdx.x * SCAN_B + threadIdx.x;
    if (i < NN) {
        int r = part[i] + bsum[blockIdx.x];
        rowp[i] = r;
        cur[i]  = r;
    }
}

// ---------------------------------------------------------------------------
__global__ void k_fill(const int* __restrict__ src, const int* __restrict__ dst,
                       const float* __restrict__ dis,
                       int* __restrict__ cur, int2* __restrict__ csr, int E) {
    int e = blockIdx.x * blockDim.x + threadIdx.x;
    if (e >= E) return;
    int s = src[e];
    int d = dst[e];
    int pos = atomicAdd(&cur[d], 1);
    csr[pos] = make_int2(s, __float_as_int(dis[s]));
}

// ---------------------------------------------------------------------------
// GEMM1 + ReLU with packed f32x2 FMA.
// Block = 128 threads (4 warps), covers 32 rows x 64 cols.
// smem tile is k-major (transposed): sx[k][row], rows padded to 34 so that
// row-pairs are 8B-aligned for LDS.64 broadcast.
// Warp w handles rows [8w, 8w+8); lane covers cols {lane, lane+32}.
// Accumulators: acc[rp][c] packed over (row 2rp, row 2rp+1).
__global__ __launch_bounds__(128) void k_gemm1(const float* __restrict__ x,
                                               const float* __restrict__ W1,
                                               const float* __restrict__ b1,
                                               float* __restrict__ h) {
    __shared__ float sx[INF_][34];
    int row0 = blockIdx.x * 32;
    int tid  = threadIdx.x;

    // load 32 rows x 256 cols, transposed into smem
    for (int i = tid; i < 32 * (INF_ / 4); i += 128) {
        int r = i >> 6;          // row 0..31
        int c = i & 63;          // float4 index 0..63
        float4 v = *(const float4*)(x + (size_t)(row0 + r) * INF_ + c * 4);
        sx[c * 4 + 0][r] = v.x;
        sx[c * 4 + 1][r] = v.y;
        sx[c * 4 + 2][r] = v.z;
        sx[c * 4 + 3][r] = v.w;
    }
    __syncthreads();

    int warp = tid >> 5, lane = tid & 31;
    int rbase = warp * 8;

    u64 acc[4][2];
#pragma unroll
    for (int rp = 0; rp < 4; rp++) { acc[rp][0] = 0ull; acc[rp][1] = 0ull; }

#pragma unroll 4
    for (int k = 0; k < INF_; k++) {
        float wa = W1[k * HIDF + lane];
        float wb = W1[k * HIDF + lane + 32];
        u64 b0 = packff(wa);
        u64 b1p = packff(wb);
#pragma unroll
        for (int rp = 0; rp < 4; rp++) {
            u64 a = *reinterpret_cast<const u64*>(&sx[k][rbase + rp * 2]);
            ffma2(acc[rp][0], a, b0);
            ffma2(acc[rp][1], a, b1p);
        }
    }

    float ba = b1[lane], bb = b1[lane + 32];
#pragma unroll
    for (int rp = 0; rp < 4; rp++) {
        float2 c0 = unpackff(acc[rp][0]);
        float2 c1 = unpackff(acc[rp][1]);
        int row = row0 + rbase + rp * 2;
        h[(size_t)row * HIDF + lane]             = fmaxf(c0.x + ba, 0.f);
        h[(size_t)(row + 1) * HIDF + lane]       = fmaxf(c0.y + ba, 0.f);
        h[(size_t)row * HIDF + lane + 32]        = fmaxf(c1.x + bb, 0.f);
        h[(size_t)(row + 1) * HIDF + lane + 32]  = fmaxf(c1.y + bb, 0.f);
    }
}

// ---------------------------------------------------------------------------
// Gather SpMM with fused combine: one warp per dst node, 4-deep edge unroll.
__global__ __launch_bounds__(256) void k_spmm_csr(const float* __restrict__ f,
                                                  const float* __restrict__ h,
                                                  const int2* __restrict__ csr,
                                                  const int* __restrict__ rowp,
                                                  const int* __restrict__ deg,
                                                  const float* __restrict__ dis,
                                                  const float* __restrict__ alpha,
                                                  const float* __restrict__ beta,
                                                  float* __restrict__ fout) {
    int node = (blockIdx.x * blockDim.x + threadIdx.x) >> 5;
    if (node >= NN) return;
    int lane = threadIdx.x & 31;

    int beg = rowp[node];
    int n   = deg[node];

    float ax = 0.f, ay = 0.f;
    int i = 0;
    for (; i + 4 <= n; i += 4) {
        int2 e0 = __ldg(&csr[beg + i]);
        int2 e1 = __ldg(&csr[beg + i + 1]);
        int2 e2 = __ldg(&csr[beg + i + 2]);
        int2 e3 = __ldg(&csr[beg + i + 3]);
        float2 v0 = ((const float2*)(f + (size_t)e0.x * HIDF))[lane];
        float2 v1 = ((const float2*)(f + (size_t)e1.x * HIDF))[lane];
        float2 v2 = ((const float2*)(f + (size_t)e2.x * HIDF))[lane];
        float2 v3 = ((const float2*)(f + (size_t)e3.x * HIDF))[lane];
        float w0 = __int_as_float(e0.y), w1 = __int_as_float(e1.y);
        float w2 = __int_as_float(e2.y), w3 = __int_as_float(e3.y);
        ax = fmaf(w0, v0.x, ax); ay = fmaf(w0, v0.y, ay);
        ax = fmaf(w1, v1.x, ax); ay = fmaf(w1, v1.y, ay);
        ax = fmaf(w2, v2.x, ax); ay = fmaf(w2, v2.y, ay);
        ax = fmaf(w3, v3.x, ax); ay = fmaf(w3, v3.y, ay);
    }
    for (; i < n; i++) {
        int2 e0 = __ldg(&csr[beg + i]);
        float2 v0 = ((const float2*)(f + (size_t)e0.x * HIDF))[lane];
        float w0 = __int_as_float(e0.y);
        ax = fmaf(w0, v0.x, ax); ay = fmaf(w0, v0.y, ay);
    }

    float scale = alpha[node] * dis[node];
    float b = beta[node];
    float2 hv = ((const float2*)(h + (size_t)node * HIDF))[lane];
    float2 r;
    r.x = fmaf(scale, ax, b * hv.x);
    r.y = fmaf(scale, ay, b * hv.y);
    ((float2*)(fout + (size_t)node * HIDF))[lane] = r;
}

// ---------------------------------------------------------------------------
// GEMM2 + log_softmax, one warp per row.
__global__ __launch_bounds__(256) void k_out(const float* __restrict__ f,
                                             const float* __restrict__ W2,
                                             const float* __restrict__ b2,
                                             float* __restrict__ out) {
    int gwarp = (blockIdx.x * blockDim.x + threadIdx.x) >> 5;
    int lane  = threadIdx.x & 31;
    if (gwarp >= NN) return;

    float2 fr = ((const float2*)(f + (size_t)gwarp * HIDF))[lane];

    float acc0 = b2[lane];
    float acc1 = (lane < 8) ? b2[lane + 32] : -1e30f;

#pragma unroll
    for (int k = 0; k < HIDF; k++) {
        float fv = __shfl_sync(0xffffffffu, (k & 1) ? fr.y : fr.x, k >> 1);
        acc0 = fmaf(fv, W2[k * OUTF + lane], acc0);
        if (lane < 8) acc1 = fmaf(fv, W2[k * OUTF + lane + 32], acc1);
    }

    float m = fmaxf(acc0, acc1);
#pragma unroll
    for (int o = 16; o > 0; o >>= 1) m = fmaxf(m, __shfl_xor_sync(0xffffffffu, m, o));
    float s = expf(acc0 - m) + ((lane < 8) ? expf(acc1 - m) : 0.f);
#pragma unroll
    for (int o = 16; o > 0; o >>= 1) s += __shfl_xor_sync(0xffffffffu, s, o);
    float ls = m + logf(s);

    out[(size_t)gwarp * OUTF + lane] = acc0 - ls;
    if (lane < 8) out[(size_t)gwarp * OUTF + lane + 32] = acc1 - ls;
}

// ---------------------------------------------------------------------------
extern "C" void kernel_launch(void* const* d_in, const int* in_sizes, int n_in,
                              void* d_out, int out_size) {
    const float* x   = (const float*)d_in[0];
    const int*   ei  = (const int*)  d_in[1];
    const float* W1  = (const float*)d_in[2];
    const float* b1  = (const float*)d_in[3];
    const float* W2  = (const float*)d_in[4];
    const float* b2  = (const float*)d_in[5];
    float* out = (float*)d_out;

    const int E = in_sizes[1] / 2;
    const int* src = ei;
    const int* dst = ei + E;

    float *h, *f1, *f2, *dis, *alpha, *beta;
    int *deg, *part, *bsum, *rowp, *cur;
    int2* csr;
    cudaGetSymbolAddress((void**)&h,     g_h);
    cudaGetSymbolAddress((void**)&f1,    g_f1);
    cudaGetSymbolAddress((void**)&f2,    g_f2);
    cudaGetSymbolAddress((void**)&dis,   g_dis);
    cudaGetSymbolAddress((void**)&alpha, g_alpha);
    cudaGetSymbolAddress((void**)&beta,  g_beta);
    cudaGetSymbolAddress((void**)&deg,   g_deg);
    cudaGetSymbolAddress((void**)&part,  g_part);
    cudaGetSymbolAddress((void**)&bsum,  g_bsum);
    cudaGetSymbolAddress((void**)&rowp,  g_rowp);
    cudaGetSymbolAddress((void**)&cur,   g_cur);
    cudaGetSymbolAddress((void**)&csr,   g_csr);

    // one-time stream/event setup (not device memory allocation)
    static cudaStream_t sB = 0;
    static cudaEvent_t evRoot = 0, evB = 0;
    static int use_fork = -1;
    if (use_fork < 0) {
        use_fork = 1;
        if (cudaStreamCreateWithFlags(&sB, cudaStreamNonBlocking) != cudaSuccess) use_fork = 0;
        if (use_fork && cudaEventCreateWithFlags(&evRoot, cudaEventDisableTiming) != cudaSuccess) use_fork = 0;
        if (use_fork && cudaEventCreateWithFlags(&evB, cudaEventDisableTiming) != cudaSuccess) use_fork = 0;
    }
    cudaStream_t sG = 0;   // stream for gemm1
    if (use_fork) {
        cudaEventRecord(evRoot, 0);
        cudaStreamWaitEvent(sB, evRoot, 0);
        sG = sB;
    }

    // gemm1 on forked stream (concurrent with graph prep)
    k_gemm1<<<NN / 32, 128, 0, sG>>>(x, W1, b1, h);
    if (use_fork) cudaEventRecord(evB, sB);

    // graph structure + coefficients on default stream
    cudaMemsetAsync(deg, 0, NN * sizeof(int), 0);
    k_degree  <<<(E + 255) / 256, 256>>>(dst, deg, E);
    k_nodecoef<<<(NN + 255) / 256, 256>>>(deg, dis, alpha, beta, NN);
    k_scan1   <<<NB_SCAN, SCAN_B>>>(deg, part, bsum);
    k_scan2   <<<1, 128>>>(bsum, NB_SCAN);
    k_scan3   <<<NB_SCAN, SCAN_B>>>(part, bsum, rowp, cur);
    k_fill    <<<(E + 255) / 256, 256>>>(src, dst, dis, cur, csr, E);

    // join: propagation needs h and csr
    if (use_fork) cudaStreamWaitEvent(0, evB, 0);

    k_spmm_csr<<<(NN * 32 + 255) / 256, 256>>>(h,  h, csr, rowp, deg, dis, alpha, beta, f1);
    k_spmm_csr<<<(NN * 32 + 255) / 256, 256>>>(f1, h, csr, rowp, deg, dis, alpha, beta, f2);

    k_out<<<(NN * 32 + 255) / 256, 256>>>(f2, W2, b2, out);
}